// round 13
// baseline (speedup 1.0000x reference)
#include <cuda_runtime.h>
#include <cuda_fp16.h>
#include <cstdint>

// Problem constants
#define MM 32
#define KK 8192
#define NN 8192
#define GROUP 128

// Tiling
#define K_SPLIT 8
#define K_CHUNK (KK / K_SPLIT)           // 1024
#define GROUPS_PER_CTA (K_CHUNK / GROUP) // 8
#define WARPS 4
#define THREADS 128
#define WARP_N 16                        // 2 n-frags per warp
#define N_TILE (WARPS * WARP_N)          // 64
#define NTILES (NN / N_TILE)             // 128
#define ASTRIDE 136                      // fp16 elems per SMEM A row (128 + 8 pad)

// Deterministic K-split partials + arrival counters + pre-converted interleaved fp16 A
__device__ __align__(16) float  g_scratch[K_SPLIT * MM * NN]; // 8 MB
__device__ unsigned int g_cnt[NTILES];                        // zero-init; reset by last CTA
__device__ __align__(16) __half g_A16[MM * KK];               // 512 KB, k-interleaved granules

// ---------------- PTX helpers ----------------
__device__ __forceinline__ void ldsm_x4(uint32_t addr, uint32_t* r) {
    asm volatile("ldmatrix.sync.aligned.m8n8.x4.shared.b16 {%0,%1,%2,%3}, [%4];"
                 : "=r"(r[0]), "=r"(r[1]), "=r"(r[2]), "=r"(r[3]) : "r"(addr));
}
__device__ __forceinline__ void lds128(uint32_t addr, uint32_t* r) {
    asm volatile("ld.shared.v4.u32 {%0,%1,%2,%3}, [%4];"
                 : "=r"(r[0]), "=r"(r[1]), "=r"(r[2]), "=r"(r[3]) : "r"(addr));
}
__device__ __forceinline__ void mma16816(float* c, const uint32_t* a, uint32_t b0, uint32_t b1) {
    asm volatile("mma.sync.aligned.m16n8k16.row.col.f32.f16.f16.f32 "
                 "{%0,%1,%2,%3}, {%4,%5,%6,%7}, {%8,%9}, {%0,%1,%2,%3};"
                 : "+f"(c[0]), "+f"(c[1]), "+f"(c[2]), "+f"(c[3])
                 : "r"(a[0]), "r"(a[1]), "r"(a[2]), "r"(a[3]), "r"(b0), "r"(b1));
}

// k-interleaved dequant (A granule stored as {k0,k4,k1,k5,k2,k6,k3,k7}):
// v = w >> (4*lr): nibble lr at bits[3:0], nibble lr+4 at bits[19:16].
// (v & 0x000F000F) | 0x64006400 = fp16x2(1024+q); subtract 1032 -> exact (q-8); scale.
__device__ __forceinline__ uint32_t dqs(uint32_t w, int sh, uint32_t s2) {
    uint32_t t = ((w >> sh) & 0x000F000Fu) | 0x64006400u;     // SHF + 1 LOP3
    __half2 x = *reinterpret_cast<__half2*>(&t);
    const __half2 c = __half2half2(__ushort_as_half(0x6408)); // 1032.0 (exact)
    __half2 y = __hmul2(__hsub2(x, c), *reinterpret_cast<__half2*>(&s2));
    return *reinterpret_cast<uint32_t*>(&y);
}

__device__ __forceinline__ void cp16(uint32_t saddr, const void* gptr) {
    asm volatile("cp.async.cg.shared.global [%0], [%1], 16;" :: "r"(saddr), "l"(gptr));
}
__device__ __forceinline__ void cp4(uint32_t saddr, const void* gptr) {
    asm volatile("cp.async.ca.shared.global [%0], [%1], 4;" :: "r"(saddr), "l"(gptr));
}
__device__ __forceinline__ void cp_commit() {
    asm volatile("cp.async.commit_group;");
}
template <int N>
__device__ __forceinline__ void cp_wait() {
    asm volatile("cp.async.wait_group %0;" :: "n"(N));
}

// ---------------- A -> fp16 pre-convert, k-interleaved per 8-granule ----------------
// 32768 granules total = 32 rows x 1024 granules (8 floats each).
__global__ void __launch_bounds__(256)
a16_convert_kernel(const float* __restrict__ A) {
    const int gi  = blockIdx.x * 256 + threadIdx.x;  // granule 0..32767
    const int row = gi >> 10, gc = gi & 1023;        // 32 rows x 1024 granules
    const float* p = A + (size_t)row * KK + gc * 8;
    const float4 a = __ldg(reinterpret_cast<const float4*>(p));
    const float4 b = __ldg(reinterpret_cast<const float4*>(p + 4));
    __half2 h0 = __floats2half2_rn(a.x, b.x);  // slots 0,1 = phys k0,k4
    __half2 h1 = __floats2half2_rn(a.y, b.y);
    __half2 h2 = __floats2half2_rn(a.z, b.z);
    __half2 h3 = __floats2half2_rn(a.w, b.w);
    uint4 o;
    o.x = *reinterpret_cast<uint32_t*>(&h0);
    o.y = *reinterpret_cast<uint32_t*>(&h1);
    o.z = *reinterpret_cast<uint32_t*>(&h2);
    o.w = *reinterpret_cast<uint32_t*>(&h3);
    *reinterpret_cast<uint4*>(&g_A16[(size_t)row * KK + gc * 8]) = o;
}

// ---------------- Fused GEMM (mma + split-K last-CTA reduce) ----------------
// sa16: double-buffered fp16 A group tile [32 x ASTRIDE] (interleaved granules)
// sq:   double-buffered permuted qweight tiles (1024 words each):
//       off = ks*128 + warp*32 + lq*4 + rl*2 + nf  -> one LDS128 per ks per lane
__global__ void __launch_bounds__(THREADS, 7)
marlin_fused_kernel(const int*   __restrict__ qweight,
                    const float* __restrict__ scales,
                    const float* __restrict__ bias,
                    float*       __restrict__ out) {
    __shared__ __align__(16) __half sa16[2][MM * ASTRIDE];  // 2 x 8704 B
    __shared__ __align__(16) int    sq[2][1024];            // 2 x 4096 B
    __shared__ unsigned int s_last;

    const int tid  = threadIdx.x;
    const int warp = tid >> 5;
    const int lane = tid & 31;
    const int lq   = lane >> 2;   // 0..7
    const int lr   = lane & 3;    // 0..3
    const int shq  = lr << 2;     // nibble shift for dequant

    const int nb_cta = blockIdx.x * N_TILE;
    const int nb     = nb_cta + warp * WARP_N;
    const int kbase  = blockIdx.y * K_CHUNK;

    const int lm_row = lane & 15;
    const int lm_k   = (lane >> 4) << 3;

    const uint32_t sa_base = (uint32_t)__cvta_generic_to_shared(&sa16[0][0]);
    const uint32_t sq_base = (uint32_t)__cvta_generic_to_shared(&sq[0][0]);

    // qweight staging: thread t covers column c = t&63, row-half rh = t>>6.
    const int st_c  = tid & 63;
    const int st_rh = tid >> 6;
    const int cperm = ((st_c >> 4) << 5) | ((st_c & 7) << 2) | ((st_c >> 3) & 1);

    // ---- async stage of one group's interleaved fp16 A ----
    auto stage_a = [&](int buf, int gk) {
        const uint32_t sa_b = sa_base + (uint32_t)buf * (MM * ASTRIDE * 2);
#pragma unroll
        for (int j = 0; j < 4; j++) {
            const int gi  = j * THREADS + tid;      // granule 0..511
            const int row = gi >> 4, gc = gi & 15;  // 32 rows x 16 granules
            cp16(sa_b + (uint32_t)(row * ASTRIDE + gc * 8) * 2,
                 g_A16 + (size_t)row * KK + gk + gc * 8);
        }
    };
    // ---- async stage of one group's permuted qweight tile ----
    auto stage_q = [&](int buf, int gk) {
        const uint32_t sq_b = sq_base + (uint32_t)buf * (1024 * 4);
        const int kp_g = gk >> 3;
        const int* qsrc = qweight + (size_t)(kp_g + st_rh * 8) * NN + nb_cta + st_c;
#pragma unroll
        for (int j = 0; j < 8; j++) {
            const int r  = st_rh * 8 + j;
            const int ks = r >> 1, rl = r & 1;
            const int off = ks * 128 + cperm + rl * 2;
            cp4(sq_b + (uint32_t)off * 4, qsrc + (size_t)j * NN);
        }
    };

    float acc[16];
#pragma unroll
    for (int i = 0; i < 16; i++) acc[i] = 0.f;

    stage_a(0, kbase);
    stage_q(0, kbase);
    cp_commit();

    for (int g = 0; g < GROUPS_PER_CTA; g++) {
        const int gk = kbase + g * GROUP;
        if (g + 1 < GROUPS_PER_CTA) {
            stage_a((g + 1) & 1, gk + GROUP);
            stage_q((g + 1) & 1, gk + GROUP);
            cp_commit();
            cp_wait<1>();
        } else {
            cp_wait<0>();
        }
        __syncthreads();

        // fp16 scales for this group's B columns (n = nb + nf*8 + lq)
        const float* sp = scales + (size_t)(gk >> 7) * NN + nb + lq;
        uint32_t s2[2];
#pragma unroll
        for (int nf = 0; nf < 2; nf++) {
            const __half2 h = __float2half2_rn(__ldg(sp + nf * 8));
            s2[nf] = *reinterpret_cast<const uint32_t*>(&h);
        }

        const uint32_t sa_b = sa_base + (uint32_t)(g & 1) * (MM * ASTRIDE * 2);
        const uint32_t sq_b = sq_base + (uint32_t)(g & 1) * (1024 * 4)
                            + (uint32_t)(warp * 32 + lq * 4) * 4;

#pragma unroll
        for (int ks = 0; ks < 8; ks++) {
            uint32_t a0[4], a1[4];
            const int kcol = (ks << 4) + lm_k;
            ldsm_x4(sa_b + (uint32_t)(lm_row * ASTRIDE + kcol) * 2, a0);
            ldsm_x4(sa_b + (uint32_t)((16 + lm_row) * ASTRIDE + kcol) * 2, a1);

            // one LDS128: q = {rl0nf0, rl0nf1, rl1nf0, rl1nf1}
            uint32_t q[4];
            lds128(sq_b + (uint32_t)(ks * 128) * 4, q);

#pragma unroll
            for (int nf = 0; nf < 2; nf++) {
                const uint32_t b0 = dqs(q[nf],     shq, s2[nf]);  // k 0-7
                const uint32_t b1 = dqs(q[2 + nf], shq, s2[nf]);  // k 8-15
                mma16816(acc + nf * 8,     a0, b0, b1);
                mma16816(acc + nf * 8 + 4, a1, b0, b1);
            }
        }
        __syncthreads();  // all warps done with buf before next restage
    }

    // ---- Deterministic K-split partials ----
    float* dst = g_scratch + (size_t)blockIdx.y * (MM * NN);
#pragma unroll
    for (int nf = 0; nf < 2; nf++) {
#pragma unroll
        for (int mt = 0; mt < 2; mt++) {
            const float* c = acc + nf * 8 + mt * 4;
            const int col  = nb + nf * 8 + (lr << 1);
            const int row0 = mt * 16 + lq;
            *reinterpret_cast<float2*>(dst + (size_t)row0 * NN + col)       = make_float2(c[0], c[1]);
            *reinterpret_cast<float2*>(dst + (size_t)(row0 + 8) * NN + col) = make_float2(c[2], c[3]);
        }
    }

    // ---- Fused split-K reduction: last-arriving CTA of this n-tile finishes ----
    __threadfence();       // partials visible before the arrival tick
    __syncthreads();       // all threads' stores issued before tid0 ticks
    if (tid == 0) {
        const unsigned old = atomicAdd(&g_cnt[blockIdx.x], 1u);
        if (old == K_SPLIT - 1) {
            g_cnt[blockIdx.x] = 0;   // reset for next launch (graph replay safe)
            s_last = 1u;
        } else {
            s_last = 0u;
        }
    }
    __syncthreads();

    if (s_last) {
        __threadfence();   // acquire: see all other CTAs' partials
#pragma unroll
        for (int it = 0; it < 4; it++) {
            const int f   = it * THREADS + tid;     // float4 index within 32x64 tile
            const int row = f >> 4, c4 = f & 15;
            const int col = nb_cta + c4 * 4;
            const float4 b = __ldg(reinterpret_cast<const float4*>(bias + col));
            float x = b.x, y = b.y, z = b.z, w = b.w;
            const float* base = g_scratch + (size_t)row * NN + col;
#pragma unroll
            for (int sp2 = 0; sp2 < K_SPLIT; sp2++) {
                const float4 v = *reinterpret_cast<const float4*>(base + (size_t)sp2 * (MM * NN));
                x += v.x; y += v.y; z += v.z; w += v.w;
            }
            *reinterpret_cast<float4*>(out + (size_t)row * NN + col) = make_float4(x, y, z, w);
        }
    }
}

extern "C" void kernel_launch(void* const* d_in, const int* in_sizes, int n_in,
                              void* d_out, int out_size) {
    const float* A       = (const float*)d_in[0];
    const int*   qweight = (const int*)  d_in[1];
    const float* scales  = (const float*)d_in[2];
    const float* bias    = (const float*)d_in[3];
    float*       out     = (float*)d_out;

    a16_convert_kernel<<<128, 256>>>(A);

    dim3 grid(NTILES, K_SPLIT);
    marlin_fused_kernel<<<grid, THREADS>>>(qweight, scales, bias, out);
}

// round 15
// speedup vs baseline: 1.3242x; 1.3242x over previous
#include <cuda_runtime.h>
#include <cuda_fp16.h>
#include <cstdint>

// Problem constants
#define MM 32
#define KK 8192
#define NN 8192
#define GROUP 128

// Tiling
#define K_SPLIT 8
#define K_CHUNK (KK / K_SPLIT)           // 1024
#define GROUPS_PER_CTA (K_CHUNK / GROUP) // 8
#define WARPS 4
#define THREADS 128
#define WARP_N 32                        // 4 n-frags per warp
#define N_TILE (WARPS * WARP_N)          // 128
#define NTILES (NN / N_TILE)             // 64
#define ASTRIDE 136                      // fp16 elems per SMEM A row (128 + 8 pad)

// Deterministic K-split partials + arrival counters (no alloc)
__device__ __align__(16) float  g_scratch[K_SPLIT * MM * NN]; // 8 MB
__device__ unsigned int g_cnt[NTILES];                        // zero-init; reset by last CTA

// ---------------- PTX helpers ----------------
__device__ __forceinline__ void ldsm_x4(uint32_t addr, uint32_t* r) {
    asm volatile("ldmatrix.sync.aligned.m8n8.x4.shared.b16 {%0,%1,%2,%3}, [%4];"
                 : "=r"(r[0]), "=r"(r[1]), "=r"(r[2]), "=r"(r[3]) : "r"(addr));
}
__device__ __forceinline__ void lds128(uint32_t addr, uint32_t* r) {
    asm volatile("ld.shared.v4.u32 {%0,%1,%2,%3}, [%4];"
                 : "=r"(r[0]), "=r"(r[1]), "=r"(r[2]), "=r"(r[3]) : "r"(addr));
}
__device__ __forceinline__ void mma16816(float* c, const uint32_t* a, uint32_t b0, uint32_t b1) {
    asm volatile("mma.sync.aligned.m16n8k16.row.col.f32.f16.f16.f32 "
                 "{%0,%1,%2,%3}, {%4,%5,%6,%7}, {%8,%9}, {%0,%1,%2,%3};"
                 : "+f"(c[0]), "+f"(c[1]), "+f"(c[2]), "+f"(c[3])
                 : "r"(a[0]), "r"(a[1]), "r"(a[2]), "r"(a[3]), "r"(b0), "r"(b1));
}

// k-interleaved dequant (A granule stored as {k0,k4,k1,k5,k2,k6,k3,k7}):
// v = w >> (4*lr): nibble lr at bits[3:0], nibble lr+4 at bits[19:16].
// (v & 0x000F000F) | 0x64006400 = fp16x2(1024+q); subtract 1032 -> exact (q-8); scale.
__device__ __forceinline__ uint32_t dqs(uint32_t w, int sh, uint32_t s2) {
    uint32_t t = ((w >> sh) & 0x000F000Fu) | 0x64006400u;     // SHF + 1 LOP3
    __half2 x = *reinterpret_cast<__half2*>(&t);
    const __half2 c = __half2half2(__ushort_as_half(0x6408)); // 1032.0 (exact)
    __half2 y = __hmul2(__hsub2(x, c), *reinterpret_cast<__half2*>(&s2));
    return *reinterpret_cast<uint32_t*>(&y);
}

__device__ __forceinline__ void cp16(uint32_t saddr, const void* gptr) {
    asm volatile("cp.async.cg.shared.global [%0], [%1], 16;" :: "r"(saddr), "l"(gptr));
}
__device__ __forceinline__ void cp_commit() {
    asm volatile("cp.async.commit_group;");
}
template <int N>
__device__ __forceinline__ void cp_wait() {
    asm volatile("cp.async.wait_group %0;" :: "n"(N));
}

// ---------------- Single fused kernel ----------------
// SMEM (static, 41.5 KB):
//   sa32: one group of A fp32 [32][128]            16 KB (single buffer)
//   sa16: one group of A fp16 [32][ASTRIDE]         8.5 KB (single buffer)
//   sq:   qweight tiles, natural [16][128], x2     16 KB (double buffer)
// N-frag remap: frag nf, frag-n n' -> physical col = wn + n'*4 + nf.
//   B word for lane (lq,lr), frag nf: row 2ks+rl, col wn+lq*4+nf -> 4 contiguous -> LDS128.
__global__ void __launch_bounds__(THREADS, 4)
marlin_fused_kernel(const float* __restrict__ A,
                    const int*   __restrict__ qweight,
                    const float* __restrict__ scales,
                    const float* __restrict__ bias,
                    float*       __restrict__ out) {
    __shared__ __align__(16) float  sa32[MM * 128];
    __shared__ __align__(16) __half sa16[MM * ASTRIDE];
    __shared__ __align__(16) int    sq[2][16 * 128];
    __shared__ unsigned int s_last;

    const int tid  = threadIdx.x;
    const int warp = tid >> 5;
    const int lane = tid & 31;
    const int lq   = lane >> 2;   // 0..7
    const int lr   = lane & 3;    // 0..3
    const int shq  = lr << 2;     // nibble shift for dequant

    const int nb_cta = blockIdx.x * N_TILE;
    const int wn     = warp * WARP_N;
    const int nb     = nb_cta + wn;
    const int kbase  = blockIdx.y * K_CHUNK;

    const int lm_row = lane & 15;
    const int lm_k   = (lane >> 4) << 3;

    const uint32_t sa16_base = (uint32_t)__cvta_generic_to_shared(&sa16[0]);
    const uint32_t sq_base   = (uint32_t)__cvta_generic_to_shared(&sq[0][0]);

    // ---- stage one group's fp32 A; thread owns granules gi = j*128+tid ----
    auto stage_a32 = [&](int gk) {
#pragma unroll
        for (int j = 0; j < 4; j++) {
            const int gi  = j * THREADS + tid;      // 0..511 granules of 8 floats
            const int row = gi >> 4, gc = gi & 15;  // 32 rows x 16 granules
            const uint32_t d = (uint32_t)__cvta_generic_to_shared(&sa32[row * 128 + gc * 8]);
            const float* s = A + (size_t)row * KK + gk + gc * 8;
            cp16(d, s);
            cp16(d + 16, s + 4);
        }
    };
    // ---- stage one group's qweight tile (natural row-major) ----
    auto stage_q = [&](int buf, int gk) {
        const int kp_g = gk >> 3;
#pragma unroll
        for (int it = 0; it < 4; it++) {
            const int i   = it * THREADS + tid;     // 0..511 int4 granules
            const int row = i >> 5, c = i & 31;     // 16 rows x 32 granules
            cp16((uint32_t)__cvta_generic_to_shared(&sq[buf][row * 128 + c * 4]),
                 qweight + (size_t)(kp_g + row) * NN + nb_cta + c * 4);
        }
    };
    // ---- convert own staged granules fp32 -> fp16 k-interleaved (no pre-sync needed) ----
    auto convert_a = [&]() {
#pragma unroll
        for (int j = 0; j < 4; j++) {
            const int gi  = j * THREADS + tid;
            const int row = gi >> 4, gc = gi & 15;
            const float4 a = *reinterpret_cast<const float4*>(&sa32[row * 128 + gc * 8]);
            const float4 b = *reinterpret_cast<const float4*>(&sa32[row * 128 + gc * 8 + 4]);
            __half2 h0 = __floats2half2_rn(a.x, b.x);  // slots {k0,k4}
            __half2 h1 = __floats2half2_rn(a.y, b.y);  // slots {k1,k5}
            __half2 h2 = __floats2half2_rn(a.z, b.z);  // slots {k2,k6}
            __half2 h3 = __floats2half2_rn(a.w, b.w);  // slots {k3,k7}
            uint4 o;
            o.x = *reinterpret_cast<uint32_t*>(&h0);
            o.y = *reinterpret_cast<uint32_t*>(&h1);
            o.z = *reinterpret_cast<uint32_t*>(&h2);
            o.w = *reinterpret_cast<uint32_t*>(&h3);
            *reinterpret_cast<uint4*>(&sa16[row * ASTRIDE + gc * 8]) = o;
        }
    };

    float acc[32];
#pragma unroll
    for (int i = 0; i < 32; i++) acc[i] = 0.f;

    // Prologue
    stage_a32(kbase);
    stage_q(0, kbase);
    cp_commit();
    cp_wait<0>();
    convert_a();           // reads only this thread's own staged bytes
    __syncthreads();       // publish sa16 + q(0); sa32 free
    stage_a32(kbase + GROUP);
    stage_q(1, kbase + GROUP);
    cp_commit();

    for (int g = 0; g < GROUPS_PER_CTA; g++) {
        const int gk = kbase + g * GROUP;

        // scales: one float4 per lane covers frag cols wn + lq*4 + {0..3}
        const float4 sf = __ldg(reinterpret_cast<const float4*>(
            scales + (size_t)(gk >> 7) * NN + nb + lq * 4));
        uint32_t s2[4];
        {
            const float* sfp = reinterpret_cast<const float*>(&sf);
#pragma unroll
            for (int nf = 0; nf < 4; nf++) {
                const __half2 h = __float2half2_rn(sfp[nf]);
                s2[nf] = *reinterpret_cast<const uint32_t*>(&h);
            }
        }

        const uint32_t sq_b = sq_base + (uint32_t)(g & 1) * (16 * 128 * 4)
                            + (uint32_t)(wn + lq * 4) * 4;

#pragma unroll
        for (int ks = 0; ks < 8; ks++) {
            uint32_t a0[4], a1[4];
            const int kcol = (ks << 4) + lm_k;
            ldsm_x4(sa16_base + (uint32_t)(lm_row * ASTRIDE + kcol) * 2, a0);
            ldsm_x4(sa16_base + (uint32_t)((16 + lm_row) * ASTRIDE + kcol) * 2, a1);

            uint32_t q0[4], q1[4];
            lds128(sq_b + (uint32_t)((2 * ks) * 128) * 4, q0);      // k 0-7,  nf 0..3
            lds128(sq_b + (uint32_t)((2 * ks + 1) * 128) * 4, q1);  // k 8-15, nf 0..3

#pragma unroll
            for (int nf = 0; nf < 4; nf++) {
                const uint32_t b0 = dqs(q0[nf], shq, s2[nf]);
                const uint32_t b1 = dqs(q1[nf], shq, s2[nf]);
                mma16816(acc + nf * 8,     a0, b0, b1);
                mma16816(acc + nf * 8 + 4, a1, b0, b1);
            }
        }

        if (g + 1 < GROUPS_PER_CTA) {
            cp_wait<0>();      // A32(g+1), q(g+1) arrived (per-thread visibility)
            __syncthreads();   // all warps done mma(g): sa16 & sq[g&1] free
            convert_a();       // sa32 -> sa16 (content g+1), own granules
            __syncthreads();   // publish sa16 + q(g+1)
            if (g + 2 < GROUPS_PER_CTA) {
                stage_a32(gk + 2 * GROUP);
                stage_q(g & 1, gk + 2 * GROUP);
                cp_commit();
            }
        }
    }

    // ---- Deterministic K-split partials (coalesced float4 via n-frag remap) ----
    // c-quad (nf, mt): c[0],c[1] row mt*16+lq cols wn+8lr+nf, wn+8lr+4+nf;
    //                  c[2],c[3] row mt*16+8+lq same cols.
    float* dst = g_scratch + (size_t)blockIdx.y * (MM * NN);
#pragma unroll
    for (int mt = 0; mt < 2; mt++) {
#pragma unroll
        for (int ci = 0; ci < 4; ci++) {
            const int row = mt * 16 + ((ci & 2) ? 8 : 0) + lq;
            const int col = nb + 8 * lr + ((ci & 1) ? 4 : 0);
            const float4 v = make_float4(acc[0 * 8 + mt * 4 + ci],
                                         acc[1 * 8 + mt * 4 + ci],
                                         acc[2 * 8 + mt * 4 + ci],
                                         acc[3 * 8 + mt * 4 + ci]);
            *reinterpret_cast<float4*>(dst + (size_t)row * NN + col) = v;
        }
    }

    // ---- Fused split-K reduction: last-arriving CTA of this n-tile finishes ----
    __threadfence();       // partials visible before the arrival tick
    __syncthreads();       // all threads' stores issued before tid0 ticks
    if (tid == 0) {
        const unsigned old = atomicAdd(&g_cnt[blockIdx.x], 1u);
        if (old == K_SPLIT - 1) {
            g_cnt[blockIdx.x] = 0;   // reset for next launch (graph replay safe)
            s_last = 1u;
        } else {
            s_last = 0u;
        }
    }
    __syncthreads();

    if (s_last) {
        __threadfence();   // acquire: see all other CTAs' partials
#pragma unroll
        for (int it = 0; it < 8; it++) {
            const int f   = it * THREADS + tid;     // float4 index within 32x128 tile
            const int row = f >> 5, c4 = f & 31;
            const int col = nb_cta + c4 * 4;
            const float4 b = __ldg(reinterpret_cast<const float4*>(bias + col));
            float x = b.x, y = b.y, z = b.z, w = b.w;
            const float* base = g_scratch + (size_t)row * NN + col;
#pragma unroll
            for (int sp2 = 0; sp2 < K_SPLIT; sp2++) {
                const float4 v = *reinterpret_cast<const float4*>(base + (size_t)sp2 * (MM * NN));
                x += v.x; y += v.y; z += v.z; w += v.w;
            }
            *reinterpret_cast<float4*>(out + (size_t)row * NN + col) = make_float4(x, y, z, w);
        }
    }
}

extern "C" void kernel_launch(void* const* d_in, const int* in_sizes, int n_in,
                              void* d_out, int out_size) {
    const float* A       = (const float*)d_in[0];
    const int*   qweight = (const int*)  d_in[1];
    const float* scales  = (const float*)d_in[2];
    const float* bias    = (const float*)d_in[3];
    float*       out     = (float*)d_out;

    dim3 grid(NTILES, K_SPLIT);
    marlin_fused_kernel<<<grid, THREADS>>>(A, qweight, scales, bias, out);
}

// round 16
// speedup vs baseline: 1.3531x; 1.0218x over previous
#include <cuda_runtime.h>
#include <cuda_fp16.h>
#include <cstdint>

// Problem constants
#define MM 32
#define KK 8192
#define NN 8192
#define GROUP 128

// Tiling
#define K_SPLIT 16
#define K_CHUNK (KK / K_SPLIT)           // 512
#define GROUPS_PER_CTA (K_CHUNK / GROUP) // 4
#define WARPS 4
#define THREADS 128
#define WARP_N 32                        // 4 n-frags per warp
#define N_TILE (WARPS * WARP_N)          // 128
#define NTILES (NN / N_TILE)             // 64
#define ASTRIDE 136                      // fp16 elems per SMEM A row (128 + 8 pad)

// Deterministic K-split partials + arrival counters + pre-converted interleaved fp16 A
__device__ __align__(16) float  g_scratch[K_SPLIT * MM * NN]; // 16 MB
__device__ unsigned int g_cnt[NTILES];                        // zero-init; reset by last CTA
__device__ __align__(16) __half g_A16[MM * KK];               // 512 KB, k-interleaved granules

// ---------------- PTX helpers ----------------
__device__ __forceinline__ void ldsm_x4(uint32_t addr, uint32_t* r) {
    asm volatile("ldmatrix.sync.aligned.m8n8.x4.shared.b16 {%0,%1,%2,%3}, [%4];"
                 : "=r"(r[0]), "=r"(r[1]), "=r"(r[2]), "=r"(r[3]) : "r"(addr));
}
__device__ __forceinline__ void lds128(uint32_t addr, uint32_t* r) {
    asm volatile("ld.shared.v4.u32 {%0,%1,%2,%3}, [%4];"
                 : "=r"(r[0]), "=r"(r[1]), "=r"(r[2]), "=r"(r[3]) : "r"(addr));
}
__device__ __forceinline__ void mma16816(float* c, const uint32_t* a, uint32_t b0, uint32_t b1) {
    asm volatile("mma.sync.aligned.m16n8k16.row.col.f32.f16.f16.f32 "
                 "{%0,%1,%2,%3}, {%4,%5,%6,%7}, {%8,%9}, {%0,%1,%2,%3};"
                 : "+f"(c[0]), "+f"(c[1]), "+f"(c[2]), "+f"(c[3])
                 : "r"(a[0]), "r"(a[1]), "r"(a[2]), "r"(a[3]), "r"(b0), "r"(b1));
}

// k-interleaved dequant (A granule stored as {k0,k4,k1,k5,k2,k6,k3,k7}):
// v = w >> (4*lr): nibble lr at bits[3:0], nibble lr+4 at bits[19:16].
// (v & 0x000F000F) | 0x64006400 = fp16x2(1024+q); subtract 1032 -> exact (q-8); scale.
__device__ __forceinline__ uint32_t dqs(uint32_t w, int sh, uint32_t s2) {
    uint32_t t = ((w >> sh) & 0x000F000Fu) | 0x64006400u;     // SHF + 1 LOP3
    __half2 x = *reinterpret_cast<__half2*>(&t);
    const __half2 c = __half2half2(__ushort_as_half(0x6408)); // 1032.0 (exact)
    __half2 y = __hmul2(__hsub2(x, c), *reinterpret_cast<__half2*>(&s2));
    return *reinterpret_cast<uint32_t*>(&y);
}

__device__ __forceinline__ void cp16(uint32_t saddr, const void* gptr) {
    asm volatile("cp.async.cg.shared.global [%0], [%1], 16;" :: "r"(saddr), "l"(gptr));
}
__device__ __forceinline__ void cp_commit() {
    asm volatile("cp.async.commit_group;");
}
template <int N>
__device__ __forceinline__ void cp_wait() {
    asm volatile("cp.async.wait_group %0;" :: "n"(N));
}

// ---------------- A -> fp16 pre-convert, k-interleaved per 8-granule ----------------
// 32768 granules total = 32 rows x 1024 granules (8 floats each).
__global__ void __launch_bounds__(256)
a16_convert_kernel(const float* __restrict__ A) {
    const int gi  = blockIdx.x * 256 + threadIdx.x;  // granule 0..32767
    const int row = gi >> 10, gc = gi & 1023;        // 32 rows x 1024 granules
    const float* p = A + (size_t)row * KK + gc * 8;
    const float4 a = __ldg(reinterpret_cast<const float4*>(p));
    const float4 b = __ldg(reinterpret_cast<const float4*>(p + 4));
    __half2 h0 = __floats2half2_rn(a.x, b.x);  // slots 0,1 = phys k0,k4
    __half2 h1 = __floats2half2_rn(a.y, b.y);
    __half2 h2 = __floats2half2_rn(a.z, b.z);
    __half2 h3 = __floats2half2_rn(a.w, b.w);
    uint4 o;
    o.x = *reinterpret_cast<uint32_t*>(&h0);
    o.y = *reinterpret_cast<uint32_t*>(&h1);
    o.z = *reinterpret_cast<uint32_t*>(&h2);
    o.w = *reinterpret_cast<uint32_t*>(&h3);
    *reinterpret_cast<uint4*>(&g_A16[(size_t)row * KK + gc * 8]) = o;
}

// ---------------- Fused GEMM (mma + split-K last-CTA reduce) ----------------
// SMEM (33.8 KB -> 6 CTAs/SM):
//   sa16: double-buffered fp16 A group tile [32][ASTRIDE] (interleaved granules)
//   sq:   double-buffered qweight tiles, natural [16][128]
// N-frag remap: frag nf -> physical cols per R15 (verified by exact rel_err match).
__global__ void __launch_bounds__(THREADS, 6)
marlin_fused_kernel(const int*   __restrict__ qweight,
                    const float* __restrict__ scales,
                    const float* __restrict__ bias,
                    float*       __restrict__ out) {
    __shared__ __align__(16) __half sa16[2][MM * ASTRIDE];  // 2 x 8704 B
    __shared__ __align__(16) int    sq[2][16 * 128];        // 2 x 8192 B
    __shared__ unsigned int s_last;

    const int tid  = threadIdx.x;
    const int warp = tid >> 5;
    const int lane = tid & 31;
    const int lq   = lane >> 2;   // 0..7
    const int lr   = lane & 3;    // 0..3
    const int shq  = lr << 2;     // nibble shift for dequant

    const int nb_cta = blockIdx.x * N_TILE;
    const int wn     = warp * WARP_N;
    const int nb     = nb_cta + wn;
    const int kbase  = blockIdx.y * K_CHUNK;

    const int lm_row = lane & 15;
    const int lm_k   = (lane >> 4) << 3;

    const uint32_t sa_base = (uint32_t)__cvta_generic_to_shared(&sa16[0][0]);
    const uint32_t sq_base = (uint32_t)__cvta_generic_to_shared(&sq[0][0]);

    // ---- stage one group's interleaved fp16 A (already converted) ----
    auto stage_a = [&](int buf, int gk) {
        const uint32_t sa_b = sa_base + (uint32_t)buf * (MM * ASTRIDE * 2);
#pragma unroll
        for (int j = 0; j < 4; j++) {
            const int gi  = j * THREADS + tid;      // granule 0..511
            const int row = gi >> 4, gc = gi & 15;  // 32 rows x 16 granules
            cp16(sa_b + (uint32_t)(row * ASTRIDE + gc * 8) * 2,
                 g_A16 + (size_t)row * KK + gk + gc * 8);
        }
    };
    // ---- stage one group's qweight tile (natural row-major) ----
    auto stage_q = [&](int buf, int gk) {
        const int kp_g = gk >> 3;
#pragma unroll
        for (int it = 0; it < 4; it++) {
            const int i   = it * THREADS + tid;     // 0..511 int4 granules
            const int row = i >> 5, c = i & 31;     // 16 rows x 32 granules
            cp16((uint32_t)__cvta_generic_to_shared(&sq[buf][row * 128 + c * 4]),
                 qweight + (size_t)(kp_g + row) * NN + nb_cta + c * 4);
        }
    };

    float acc[32];
#pragma unroll
    for (int i = 0; i < 32; i++) acc[i] = 0.f;

    stage_a(0, kbase);
    stage_q(0, kbase);
    cp_commit();

    for (int g = 0; g < GROUPS_PER_CTA; g++) {
        const int gk = kbase + g * GROUP;
        if (g + 1 < GROUPS_PER_CTA) {
            stage_a((g + 1) & 1, gk + GROUP);
            stage_q((g + 1) & 1, gk + GROUP);
            cp_commit();
            cp_wait<1>();
        } else {
            cp_wait<0>();
        }
        __syncthreads();

        // scales: one float4 per lane covers frag cols wn + lq*4 + {0..3}
        const float4 sf = __ldg(reinterpret_cast<const float4*>(
            scales + (size_t)(gk >> 7) * NN + nb + lq * 4));
        uint32_t s2[4];
        {
            const float* sfp = reinterpret_cast<const float*>(&sf);
#pragma unroll
            for (int nf = 0; nf < 4; nf++) {
                const __half2 h = __float2half2_rn(sfp[nf]);
                s2[nf] = *reinterpret_cast<const uint32_t*>(&h);
            }
        }

        const uint32_t sa_b = sa_base + (uint32_t)(g & 1) * (MM * ASTRIDE * 2);
        const uint32_t sq_b = sq_base + (uint32_t)(g & 1) * (16 * 128 * 4)
                            + (uint32_t)(wn + lq * 4) * 4;

#pragma unroll
        for (int ks = 0; ks < 8; ks++) {
            uint32_t a0[4], a1[4];
            const int kcol = (ks << 4) + lm_k;
            ldsm_x4(sa_b + (uint32_t)(lm_row * ASTRIDE + kcol) * 2, a0);
            ldsm_x4(sa_b + (uint32_t)((16 + lm_row) * ASTRIDE + kcol) * 2, a1);

            uint32_t q0[4], q1[4];
            lds128(sq_b + (uint32_t)((2 * ks) * 128) * 4, q0);      // k 0-7,  nf 0..3
            lds128(sq_b + (uint32_t)((2 * ks + 1) * 128) * 4, q1);  // k 8-15, nf 0..3

#pragma unroll
            for (int nf = 0; nf < 4; nf++) {
                const uint32_t b0 = dqs(q0[nf], shq, s2[nf]);
                const uint32_t b1 = dqs(q1[nf], shq, s2[nf]);
                mma16816(acc + nf * 8,     a0, b0, b1);
                mma16816(acc + nf * 8 + 4, a1, b0, b1);
            }
        }
        __syncthreads();  // all warps done with buf before next restage
    }

    // ---- Deterministic K-split partials (coalesced float4 via n-frag remap) ----
    float* dst = g_scratch + (size_t)blockIdx.y * (MM * NN);
#pragma unroll
    for (int mt = 0; mt < 2; mt++) {
#pragma unroll
        for (int ci = 0; ci < 4; ci++) {
            const int row = mt * 16 + ((ci & 2) ? 8 : 0) + lq;
            const int col = nb + 8 * lr + ((ci & 1) ? 4 : 0);
            const float4 v = make_float4(acc[0 * 8 + mt * 4 + ci],
                                         acc[1 * 8 + mt * 4 + ci],
                                         acc[2 * 8 + mt * 4 + ci],
                                         acc[3 * 8 + mt * 4 + ci]);
            *reinterpret_cast<float4*>(dst + (size_t)row * NN + col) = v;
        }
    }

    // ---- Fused split-K reduction: last-arriving CTA of this n-tile finishes ----
    __threadfence();       // partials visible before the arrival tick
    __syncthreads();       // all threads' stores issued before tid0 ticks
    if (tid == 0) {
        const unsigned old = atomicAdd(&g_cnt[blockIdx.x], 1u);
        if (old == K_SPLIT - 1) {
            g_cnt[blockIdx.x] = 0;   // reset for next launch (graph replay safe)
            s_last = 1u;
        } else {
            s_last = 0u;
        }
    }
    __syncthreads();

    if (s_last) {
        __threadfence();   // acquire: see all other CTAs' partials
#pragma unroll
        for (int it = 0; it < 8; it++) {
            const int f   = it * THREADS + tid;     // float4 index within 32x128 tile
            const int row = f >> 5, c4 = f & 31;
            const int col = nb_cta + c4 * 4;
            const float4 b = __ldg(reinterpret_cast<const float4*>(bias + col));
            float x = b.x, y = b.y, z = b.z, w = b.w;
            const float* base = g_scratch + (size_t)row * NN + col;
#pragma unroll
            for (int sp2 = 0; sp2 < K_SPLIT; sp2++) {
                const float4 v = *reinterpret_cast<const float4*>(base + (size_t)sp2 * (MM * NN));
                x += v.x; y += v.y; z += v.z; w += v.w;
            }
            *reinterpret_cast<float4*>(out + (size_t)row * NN + col) = make_float4(x, y, z, w);
        }
    }
}

extern "C" void kernel_launch(void* const* d_in, const int* in_sizes, int n_in,
                              void* d_out, int out_size) {
    const float* A       = (const float*)d_in[0];
    const int*   qweight = (const int*)  d_in[1];
    const float* scales  = (const float*)d_in[2];
    const float* bias    = (const float*)d_in[3];
    float*       out     = (float*)d_out;

    a16_convert_kernel<<<128, 256>>>(A);

    dim3 grid(NTILES, K_SPLIT);
    marlin_fused_kernel<<<grid, THREADS>>>(qweight, scales, bias, out);
}